// round 5
// baseline (speedup 1.0000x reference)
#include <cuda_runtime.h>
#include <cuda_bf16.h>
#include <cstdint>

#define INDIM 128
#define HIDC  256
#define NBAT  4096
#define N2C   12288
#define FANC  10
#define N1C   122880

// ---------------- scratch (static device allocations; no cudaMalloc) ----------------
__device__ float g_h0[(size_t)N1C * HIDC];
__device__ float g_h2[(size_t)N2C * HIDC];

// ---------------- bf16 split helpers ----------------
__device__ __forceinline__ void split_pack(float a, float b, uint32_t& hi, uint32_t& lo) {
    __nv_bfloat16 ha = __float2bfloat16_rn(a);
    __nv_bfloat16 hb = __float2bfloat16_rn(b);
    float la = a - __bfloat162float(ha);
    float lb = b - __bfloat162float(hb);
    __nv_bfloat16 sa = __float2bfloat16_rn(la);
    __nv_bfloat16 sb = __float2bfloat16_rn(lb);
    hi = ((uint32_t)__bfloat16_as_ushort(hb) << 16) | (uint32_t)__bfloat16_as_ushort(ha);
    lo = ((uint32_t)__bfloat16_as_ushort(sb) << 16) | (uint32_t)__bfloat16_as_ushort(sa);
}

__device__ __forceinline__ void store_split4(uint32_t* Ahi, uint32_t* Alo, int idx, float4 v) {
    uint32_t h0, l0, h1, l1;
    split_pack(v.x, v.y, h0, l0);
    split_pack(v.z, v.w, h1, l1);
    *(uint2*)&Ahi[idx] = make_uint2(h0, h1);
    *(uint2*)&Alo[idx] = make_uint2(l0, l1);
}

#define MMA_BF16(c, a, b0v, b1v) \
    asm volatile("mma.sync.aligned.m16n8k16.row.col.f32.bf16.bf16.f32 " \
        "{%0,%1,%2,%3}, {%4,%5,%6,%7}, {%8,%9}, {%0,%1,%2,%3};" \
        : "+f"((c)[0]), "+f"((c)[1]), "+f"((c)[2]), "+f"((c)[3]) \
        : "r"((a)[0]), "r"((a)[1]), "r"((a)[2]), "r"((a)[3]), "r"(b0v), "r"(b1v))

// ---------------- fused gather + bf16x3-split tensor-core GEMM (layers 0/1) ----------------
// BM=64 per CTA, BN=256, 256 threads, 2 CTAs/SM for phase overlap.
// out[64/CTA, 256] = (relu?)( A_self @ W0 + A_mean @ W1 + bias )
// MODE 0: self=node_feat[gids[i]] (KP=128), mean over node_feat[gids[neigh[i][f]]]
// MODE 1: self=h0[i] (KP=256),              mean over h0[neigh[i][f]]
template<int MODE, int KP, bool RELU>
__global__ void __launch_bounds__(256, 2)
mma_gemm(const float* __restrict__ src,
         const int*   __restrict__ gids,
         const int*   __restrict__ neigh,
         const float* __restrict__ W0,   // [KP][256] row-major
         const float* __restrict__ W1,   // [KP][256] row-major (neighbor pass)
         const float* __restrict__ bias,
         float*       __restrict__ out)
{
    constexpr int LDA_U = KP / 2 + 4;            // packed-u32 row stride of A
    constexpr int A_U   = 64 * LDA_U;
    constexpr int LDB_U = 264;                   // packed-u32 row stride of B chunk
    constexpr int B_U   = 16 * LDB_U;

    extern __shared__ uint32_t smem[];
    uint32_t* Ahi = smem;
    uint32_t* Alo = Ahi + A_U;
    uint32_t* Bhi = Alo + A_U;
    uint32_t* Blo = Bhi + B_U;
    float*    bsm = (float*)(Blo + B_U);
    int*      sidx = (int*)(bsm + 256);          // 64 resolved self row ids
    int*      gidx = sidx + 64;                  // 640 resolved neighbor row ids

    const int tid  = threadIdx.x;
    const int lane = tid & 31;
    const int wid  = tid >> 5;
    const int wr   = wid >> 2;      // warp row 0..1  (32 rows each)
    const int wc   = wid & 3;       // warp col 0..3  (64 cols each)
    const float4* src4 = (const float4*)src;

    bsm[tid] = bias[tid];

    // ---------- pre-resolve all indices (kills dependent-load chains) ----------
    if (tid < 64) {
        int i = blockIdx.x * 64 + tid;
        sidx[tid] = (MODE == 0) ? __ldg(&gids[i]) : i;
    }
    for (int e = tid; e < 64 * FANC; e += 256) {
        int nj = __ldg(&neigh[(size_t)blockIdx.x * 64 * FANC + e]);
        gidx[e] = (MODE == 0) ? __ldg(&gids[nj]) : nj;
    }
    __syncthreads();

    float acc[2][8][4];
    #pragma unroll
    for (int mt = 0; mt < 2; mt++)
        #pragma unroll
        for (int nt = 0; nt < 8; nt++)
            #pragma unroll
            for (int q = 0; q < 4; q++) acc[mt][nt][q] = 0.f;

    #pragma unroll 1
    for (int pass = 0; pass < 2; pass++) {
        const float* W = (pass == 0) ? W0 : W1;

        // ---------- gather A tile (fp32 -> split bf16 hi/lo, packed pairs) ----------
        if (MODE == 0) {
            if (pass == 0) {
                #pragma unroll
                for (int j = 0; j < 8; j++) {
                    int r = wid + 8 * j;
                    int g = sidx[r];
                    float4 v = __ldg(&src4[(size_t)g * 32 + lane]);
                    store_split4(Ahi, Alo, r * LDA_U + 2 * lane, v);
                }
            } else {
                #pragma unroll 1
                for (int g = 0; g < 2; g++) {
                    float4 a[4];
                    #pragma unroll
                    for (int j = 0; j < 4; j++) a[j] = make_float4(0.f, 0.f, 0.f, 0.f);
                    #pragma unroll
                    for (int f = 0; f < FANC; f++) {
                        #pragma unroll
                        for (int j = 0; j < 4; j++) {
                            int rr = wid + 8 * (g * 4 + j);
                            int gn = gidx[rr * FANC + f];
                            float4 t = __ldg(&src4[(size_t)gn * 32 + lane]);
                            a[j].x += t.x; a[j].y += t.y; a[j].z += t.z; a[j].w += t.w;
                        }
                    }
                    #pragma unroll
                    for (int j = 0; j < 4; j++) {
                        int rr = wid + 8 * (g * 4 + j);
                        store_split4(Ahi, Alo, rr * LDA_U + 2 * lane,
                                     make_float4(a[j].x * 0.1f, a[j].y * 0.1f,
                                                 a[j].z * 0.1f, a[j].w * 0.1f));
                    }
                }
            }
        } else {
            if (pass == 0) {
                #pragma unroll
                for (int j = 0; j < 8; j++) {
                    int r = wid + 8 * j;
                    int i = sidx[r];
                    #pragma unroll
                    for (int h = 0; h < 2; h++) {
                        float4 v = __ldg(&src4[(size_t)i * 64 + lane + 32 * h]);
                        store_split4(Ahi, Alo, r * LDA_U + 2 * (lane + 32 * h), v);
                    }
                }
            } else {
                #pragma unroll 1
                for (int g = 0; g < 4; g++) {
                    float4 a0[2], a1[2];
                    #pragma unroll
                    for (int j = 0; j < 2; j++) {
                        a0[j] = make_float4(0.f, 0.f, 0.f, 0.f);
                        a1[j] = make_float4(0.f, 0.f, 0.f, 0.f);
                    }
                    #pragma unroll
                    for (int f = 0; f < FANC; f++) {
                        #pragma unroll
                        for (int j = 0; j < 2; j++) {
                            int rr = wid + 8 * (g * 2 + j);
                            int nj = gidx[rr * FANC + f];
                            const float4* p = src4 + (size_t)nj * 64;
                            float4 t0 = __ldg(p + lane);
                            float4 t1 = __ldg(p + lane + 32);
                            a0[j].x += t0.x; a0[j].y += t0.y; a0[j].z += t0.z; a0[j].w += t0.w;
                            a1[j].x += t1.x; a1[j].y += t1.y; a1[j].z += t1.z; a1[j].w += t1.w;
                        }
                    }
                    #pragma unroll
                    for (int j = 0; j < 2; j++) {
                        int rr = wid + 8 * (g * 2 + j);
                        store_split4(Ahi, Alo, rr * LDA_U + 2 * lane,
                                     make_float4(a0[j].x * 0.1f, a0[j].y * 0.1f,
                                                 a0[j].z * 0.1f, a0[j].w * 0.1f));
                        store_split4(Ahi, Alo, rr * LDA_U + 2 * (lane + 32),
                                     make_float4(a1[j].x * 0.1f, a1[j].y * 0.1f,
                                                 a1[j].z * 0.1f, a1[j].w * 0.1f));
                    }
                }
            }
        }

        // ---------- K chunks of 32: stage B (split), then MMA ----------
        #pragma unroll 1
        for (int c = 0; c < KP / 32; c++) {
            for (int e = tid; e < 16 * 256; e += 256) {
                int kp  = e >> 8;
                int col = e & 255;
                int krow = c * 32 + 2 * kp;
                float w0 = __ldg(&W[(size_t)krow * 256 + col]);
                float w1 = __ldg(&W[(size_t)(krow + 1) * 256 + col]);
                uint32_t h, l;
                split_pack(w0, w1, h, l);
                Bhi[kp * LDB_U + col] = h;
                Blo[kp * LDB_U + col] = l;
            }
            __syncthreads();

            #pragma unroll
            for (int ks = 0; ks < 2; ks++) {
                const int kpo = c * 16 + ks * 8;
                uint32_t ah[2][4], al[2][4];
                const int abase = (wr * 32 + (lane >> 2)) * LDA_U + (lane & 3) + kpo;
                #pragma unroll
                for (int mt = 0; mt < 2; mt++) {
                    int a0i = abase + mt * 16 * LDA_U;
                    ah[mt][0] = Ahi[a0i];
                    ah[mt][1] = Ahi[a0i + 8 * LDA_U];
                    ah[mt][2] = Ahi[a0i + 4];
                    ah[mt][3] = Ahi[a0i + 8 * LDA_U + 4];
                    al[mt][0] = Alo[a0i];
                    al[mt][1] = Alo[a0i + 8 * LDA_U];
                    al[mt][2] = Alo[a0i + 4];
                    al[mt][3] = Alo[a0i + 8 * LDA_U + 4];
                }
                const int bbase = (ks * 8 + (lane & 3)) * LDB_U + wc * 64 + (lane >> 2);
                #pragma unroll
                for (int nt = 0; nt < 8; nt++) {
                    int bi = bbase + nt * 8;
                    uint32_t bh0 = Bhi[bi], bh1 = Bhi[bi + 4 * LDB_U];
                    uint32_t bl0 = Blo[bi], bl1 = Blo[bi + 4 * LDB_U];
                    #pragma unroll
                    for (int mt = 0; mt < 2; mt++) {
                        MMA_BF16(acc[mt][nt], ah[mt], bh0, bh1);
                        MMA_BF16(acc[mt][nt], ah[mt], bl0, bl1);
                        MMA_BF16(acc[mt][nt], al[mt], bh0, bh1);
                    }
                }
            }
            __syncthreads();
        }
    }

    // ---------- epilogue: bias (+relu), float2 stores ----------
    const int row0 = blockIdx.x * 64 + wr * 32 + (lane >> 2);
    #pragma unroll
    for (int mt = 0; mt < 2; mt++) {
        #pragma unroll
        for (int nt = 0; nt < 8; nt++) {
            int col = wc * 64 + nt * 8 + 2 * (lane & 3);
            float b0 = bsm[col], b1 = bsm[col + 1];
            float v0 = acc[mt][nt][0] + b0;
            float v1 = acc[mt][nt][1] + b1;
            float v2 = acc[mt][nt][2] + b0;
            float v3 = acc[mt][nt][3] + b1;
            if (RELU) {
                v0 = fmaxf(v0, 0.f); v1 = fmaxf(v1, 0.f);
                v2 = fmaxf(v2, 0.f); v3 = fmaxf(v3, 0.f);
            }
            int r = row0 + mt * 16;
            *(float2*)&out[(size_t)r * HIDC + col]       = make_float2(v0, v1);
            *(float2*)&out[(size_t)(r + 8) * HIDC + col] = make_float2(v2, v3);
        }
    }
}

// ---------------- fused MLP1 + MLP2 + score (row-local chain) ----------------
// block: 64 rows of the 8192 edge rows; 256 threads, 2 CTAs/SM
__global__ void __launch_bounds__(256, 2)
mlp_fused(const float* __restrict__ h2,
          const float* __restrict__ Wp1, const float* __restrict__ bp1,
          const float* __restrict__ Wp2, const float* __restrict__ bp2,
          const float* __restrict__ Wp3, const float* __restrict__ bp3,
          float* __restrict__ out)
{
    constexpr int LDA_U = 132;          // K=256 packed pairs + pad
    constexpr int A_U   = 64 * LDA_U;
    constexpr int LDB_U = 264;
    constexpr int B_U   = 16 * LDB_U;

    extern __shared__ uint32_t smem[];
    uint32_t* Ahi = smem;
    uint32_t* Alo = Ahi + A_U;
    uint32_t* Bhi = Alo + A_U;
    uint32_t* Blo = Bhi + B_U;
    float* bsm1 = (float*)(Blo + B_U);
    float* bsm2 = bsm1 + 256;
    float* w3   = bsm2 + 256;
    float* sred = w3 + 256;

    const int tid  = threadIdx.x;
    const int lane = tid & 31;
    const int wid  = tid >> 5;
    const int wr   = wid >> 2;   // 0..1  (32 rows each)
    const int wc   = wid & 3;    // 0..3  (64 cols each)
    const float4* src4 = (const float4*)h2;

    bsm1[tid] = bp1[tid];
    bsm2[tid] = bp2[tid];
    w3[tid]   = Wp3[tid];
    if (tid < 64) sred[tid] = bp3[0];

    // ---------- build A = src * posneg ----------
    for (int r = wid; r < 64; r += 8) {
        int i = blockIdx.x * 64 + r;
        const float4* pa = src4 + (size_t)(i & (NBAT - 1)) * 64;
        const float4* pb = src4 + (size_t)(NBAT + i) * 64;
        #pragma unroll
        for (int h = 0; h < 2; h++) {
            float4 x = __ldg(pa + lane + 32 * h);
            float4 y = __ldg(pb + lane + 32 * h);
            store_split4(Ahi, Alo, r * LDA_U + 2 * (lane + 32 * h),
                         make_float4(x.x * y.x, x.y * y.y, x.z * y.z, x.w * y.w));
        }
    }

    float acc[2][8][4];

    // ---------- two GEMM layers ----------
    #pragma unroll 1
    for (int layer = 0; layer < 2; layer++) {
        const float* W = (layer == 0) ? Wp1 : Wp2;

        #pragma unroll
        for (int mt = 0; mt < 2; mt++)
            #pragma unroll
            for (int nt = 0; nt < 8; nt++)
                #pragma unroll
                for (int q = 0; q < 4; q++) acc[mt][nt][q] = 0.f;

        #pragma unroll 1
        for (int c = 0; c < 8; c++) {
            for (int e = tid; e < 16 * 256; e += 256) {
                int kp  = e >> 8;
                int col = e & 255;
                int krow = c * 32 + 2 * kp;
                float w0 = __ldg(&W[(size_t)krow * 256 + col]);
                float w1 = __ldg(&W[(size_t)(krow + 1) * 256 + col]);
                uint32_t h, l;
                split_pack(w0, w1, h, l);
                Bhi[kp * LDB_U + col] = h;
                Blo[kp * LDB_U + col] = l;
            }
            __syncthreads();

            #pragma unroll
            for (int ks = 0; ks < 2; ks++) {
                const int kpo = c * 16 + ks * 8;
                uint32_t ah[2][4], al[2][4];
                const int abase = (wr * 32 + (lane >> 2)) * LDA_U + (lane & 3) + kpo;
                #pragma unroll
                for (int mt = 0; mt < 2; mt++) {
                    int a0i = abase + mt * 16 * LDA_U;
                    ah[mt][0] = Ahi[a0i];
                    ah[mt][1] = Ahi[a0i + 8 * LDA_U];
                    ah[mt][2] = Ahi[a0i + 4];
                    ah[mt][3] = Ahi[a0i + 8 * LDA_U + 4];
                    al[mt][0] = Alo[a0i];
                    al[mt][1] = Alo[a0i + 8 * LDA_U];
                    al[mt][2] = Alo[a0i + 4];
                    al[mt][3] = Alo[a0i + 8 * LDA_U + 4];
                }
                const int bbase = (ks * 8 + (lane & 3)) * LDB_U + wc * 64 + (lane >> 2);
                #pragma unroll
                for (int nt = 0; nt < 8; nt++) {
                    int bi = bbase + nt * 8;
                    uint32_t bh0 = Bhi[bi], bh1 = Bhi[bi + 4 * LDB_U];
                    uint32_t bl0 = Blo[bi], bl1 = Blo[bi + 4 * LDB_U];
                    #pragma unroll
                    for (int mt = 0; mt < 2; mt++) {
                        MMA_BF16(acc[mt][nt], ah[mt], bh0, bh1);
                        MMA_BF16(acc[mt][nt], ah[mt], bl0, bl1);
                        MMA_BF16(acc[mt][nt], al[mt], bh0, bh1);
                    }
                }
            }
            __syncthreads();
        }

        if (layer == 0) {
            // write z1 = relu(acc + bp1) back into the split-A region
            #pragma unroll
            for (int mt = 0; mt < 2; mt++) {
                int r = wr * 32 + (lane >> 2) + mt * 16;
                #pragma unroll
                for (int nt = 0; nt < 8; nt++) {
                    int col = wc * 64 + nt * 8 + 2 * (lane & 3);
                    float b0 = bsm1[col], b1 = bsm1[col + 1];
                    float v0 = fmaxf(acc[mt][nt][0] + b0, 0.f);
                    float v1 = fmaxf(acc[mt][nt][1] + b1, 0.f);
                    float v2 = fmaxf(acc[mt][nt][2] + b0, 0.f);
                    float v3 = fmaxf(acc[mt][nt][3] + b1, 0.f);
                    uint32_t h, l;
                    split_pack(v0, v1, h, l);
                    Ahi[r * LDA_U + (col >> 1)] = h;
                    Alo[r * LDA_U + (col >> 1)] = l;
                    split_pack(v2, v3, h, l);
                    Ahi[(r + 8) * LDA_U + (col >> 1)] = h;
                    Alo[(r + 8) * LDA_U + (col >> 1)] = l;
                }
            }
            __syncthreads();
        }
    }

    // ---------- score: z2 = relu(acc + bp2); s = z2 . Wp3 ----------
    #pragma unroll
    for (int mt = 0; mt < 2; mt++) {
        float sA = 0.f, sB = 0.f;
        #pragma unroll
        for (int nt = 0; nt < 8; nt++) {
            int col = wc * 64 + nt * 8 + 2 * (lane & 3);
            float b0 = bsm2[col], b1 = bsm2[col + 1];
            float w0 = w3[col],  w1 = w3[col + 1];
            sA += fmaxf(acc[mt][nt][0] + b0, 0.f) * w0 + fmaxf(acc[mt][nt][1] + b1, 0.f) * w1;
            sB += fmaxf(acc[mt][nt][2] + b0, 0.f) * w0 + fmaxf(acc[mt][nt][3] + b1, 0.f) * w1;
        }
        sA += __shfl_xor_sync(0xffffffffu, sA, 1);
        sA += __shfl_xor_sync(0xffffffffu, sA, 2);
        sB += __shfl_xor_sync(0xffffffffu, sB, 1);
        sB += __shfl_xor_sync(0xffffffffu, sB, 2);
        if ((lane & 3) == 0) {
            int r = wr * 32 + (lane >> 2) + mt * 16;
            atomicAdd(&sred[r], sA);
            atomicAdd(&sred[r + 8], sB);
        }
    }
    __syncthreads();
    if (tid < 64) out[blockIdx.x * 64 + tid] = sred[tid];
}

// ---------------- launch ----------------
extern "C" void kernel_launch(void* const* d_in, const int* in_sizes, int n_in,
                              void* d_out, int out_size) {
    const float* node_feat = (const float*)d_in[0];
    const int*   gids0     = (const int*)d_in[1];
    const int*   neigh0    = (const int*)d_in[2];
    const int*   neigh1    = (const int*)d_in[3];
    const float* Ws0       = (const float*)d_in[4];
    const float* Wn0       = (const float*)d_in[5];
    const float* b0        = (const float*)d_in[6];
    const float* Ws1       = (const float*)d_in[7];
    const float* Wn1       = (const float*)d_in[8];
    const float* b1        = (const float*)d_in[9];
    const float* Wp1       = (const float*)d_in[10];
    const float* bp1       = (const float*)d_in[11];
    const float* Wp2       = (const float*)d_in[12];
    const float* bp2       = (const float*)d_in[13];
    const float* Wp3       = (const float*)d_in[14];
    const float* bp3       = (const float*)d_in[15];
    float* out = (float*)d_out;

    float *h0, *h2;
    cudaGetSymbolAddress((void**)&h0, g_h0);
    cudaGetSymbolAddress((void**)&h2, g_h2);

    // smem bytes: 2*A + 2*B + bias + sidx + gidx
    const int SM128 = (2 * 64 * (128 / 2 + 4) + 2 * 16 * 264 + 256 + 64 + 64 * FANC) * 4;  //  72,448
    const int SM256 = (2 * 64 * (256 / 2 + 4) + 2 * 16 * 264 + 256 + 64 + 64 * FANC) * 4;  // 105,216
    const int SMMLP = (2 * 64 * 132 + 2 * 16 * 264 + 3 * 256 + 64) * 4;                     // 104,704

    cudaFuncSetAttribute(mma_gemm<0, 128, true >, cudaFuncAttributeMaxDynamicSharedMemorySize, SM128);
    cudaFuncSetAttribute(mma_gemm<1, 256, false>, cudaFuncAttributeMaxDynamicSharedMemorySize, SM256);
    cudaFuncSetAttribute(mlp_fused, cudaFuncAttributeMaxDynamicSharedMemorySize, SMMLP);

    // layer 0: h0 = relu(self@Ws0 + mean@Wn0 + b0)
    mma_gemm<0, 128, true ><<<N1C / 64, 256, SM128>>>(node_feat, gids0, neigh0, Ws0, Wn0, b0, h0);
    // layer 1: h2 = self@Ws1 + mean@Wn1 + b1
    mma_gemm<1, 256, false><<<N2C / 64, 256, SM256>>>(h0, nullptr, neigh1, Ws1, Wn1, b1, h2);
    // fused MLP1+MLP2+score
    mlp_fused<<<(2 * NBAT) / 64, 256, SMMLP>>>(h2, Wp1, bp1, Wp2, bp2, Wp3, bp3, out);
}

// round 7
// speedup vs baseline: 1.0582x; 1.0582x over previous
#include <cuda_runtime.h>
#include <cuda_bf16.h>
#include <cstdint>

#define INDIM 128
#define HIDC  256
#define NBAT  4096
#define N2C   12288
#define FANC  10
#define N1C   122880

// ---------------- scratch (static device allocations; no cudaMalloc) ----------------
__device__ float g_h0[(size_t)N1C * HIDC];       // 126 MB
__device__ float g_h2[(size_t)N2C * HIDC];
__device__ float g_mean0[(size_t)N1C * INDIM];   // 63 MB
__device__ float g_mean1[(size_t)N2C * HIDC];    // 12.6 MB

// ---------------- bf16 split helpers ----------------
__device__ __forceinline__ void split_pack(float a, float b, uint32_t& hi, uint32_t& lo) {
    __nv_bfloat16 ha = __float2bfloat16_rn(a);
    __nv_bfloat16 hb = __float2bfloat16_rn(b);
    float la = a - __bfloat162float(ha);
    float lb = b - __bfloat162float(hb);
    __nv_bfloat16 sa = __float2bfloat16_rn(la);
    __nv_bfloat16 sb = __float2bfloat16_rn(lb);
    hi = ((uint32_t)__bfloat16_as_ushort(hb) << 16) | (uint32_t)__bfloat16_as_ushort(ha);
    lo = ((uint32_t)__bfloat16_as_ushort(sb) << 16) | (uint32_t)__bfloat16_as_ushort(sa);
}

__device__ __forceinline__ void store_split4(uint32_t* Ahi, uint32_t* Alo, int idx, float4 v) {
    uint32_t h0, l0, h1, l1;
    split_pack(v.x, v.y, h0, l0);
    split_pack(v.z, v.w, h1, l1);
    *(uint2*)&Ahi[idx] = make_uint2(h0, h1);
    *(uint2*)&Alo[idx] = make_uint2(l0, l1);
}

#define MMA_BF16(c, a, b0v, b1v) \
    asm volatile("mma.sync.aligned.m16n8k16.row.col.f32.bf16.bf16.f32 " \
        "{%0,%1,%2,%3}, {%4,%5,%6,%7}, {%8,%9}, {%0,%1,%2,%3};" \
        : "+f"((c)[0]), "+f"((c)[1]), "+f"((c)[2]), "+f"((c)[3]) \
        : "r"((a)[0]), "r"((a)[1]), "r"((a)[2]), "r"((a)[3]), "r"(b0v), "r"(b1v))

// ---------------- standalone high-occupancy neighbor-mean gather ----------------
// outb[i] = 0.1 * sum_f src[ idx(neigh[i][f]) ]   (rows of NH4*32 float4)
// NH4=1: 128-float rows (layer0);  NH4=2: 256-float rows (layer1)
template<int NH4, bool RESOLVE>
__global__ void __launch_bounds__(256, 4)
gather_mean(const float* __restrict__ src,
            const int*   __restrict__ gids,
            const int*   __restrict__ neigh,
            float*       __restrict__ outb)
{
    __shared__ int idx[64 * FANC];
    const int tid  = threadIdx.x;
    const int lane = tid & 31;
    const int wid  = tid >> 5;
    const int base = blockIdx.x * 64;
    const float4* src4 = (const float4*)src;
    float4* out4 = (float4*)outb;

    for (int e = tid; e < 64 * FANC; e += 256) {
        int nj = __ldg(&neigh[(size_t)base * FANC + e]);
        idx[e] = RESOLVE ? __ldg(&gids[nj]) : nj;
    }
    __syncthreads();

    // 8 warps x 8 rows; process rows in pairs -> 20 independent 512B loads in flight
    #pragma unroll 1
    for (int g = 0; g < 4; g++) {
        if (NH4 == 1) {
            float4 a[2];
            a[0] = make_float4(0.f, 0.f, 0.f, 0.f);
            a[1] = make_float4(0.f, 0.f, 0.f, 0.f);
            #pragma unroll
            for (int f = 0; f < FANC; f++) {
                #pragma unroll
                for (int j = 0; j < 2; j++) {
                    int rr = wid + 8 * (g * 2 + j);
                    int gn = idx[rr * FANC + f];
                    float4 t = __ldg(&src4[(size_t)gn * 32 + lane]);
                    a[j].x += t.x; a[j].y += t.y; a[j].z += t.z; a[j].w += t.w;
                }
            }
            #pragma unroll
            for (int j = 0; j < 2; j++) {
                int rr = wid + 8 * (g * 2 + j);
                out4[(size_t)(base + rr) * 32 + lane] =
                    make_float4(a[j].x * 0.1f, a[j].y * 0.1f, a[j].z * 0.1f, a[j].w * 0.1f);
            }
        } else {
            float4 a0[2], a1[2];
            #pragma unroll
            for (int j = 0; j < 2; j++) {
                a0[j] = make_float4(0.f, 0.f, 0.f, 0.f);
                a1[j] = make_float4(0.f, 0.f, 0.f, 0.f);
            }
            #pragma unroll
            for (int f = 0; f < FANC; f++) {
                #pragma unroll
                for (int j = 0; j < 2; j++) {
                    int rr = wid + 8 * (g * 2 + j);
                    int nj = idx[rr * FANC + f];
                    const float4* p = src4 + (size_t)nj * 64;
                    float4 t0 = __ldg(p + lane);
                    float4 t1 = __ldg(p + lane + 32);
                    a0[j].x += t0.x; a0[j].y += t0.y; a0[j].z += t0.z; a0[j].w += t0.w;
                    a1[j].x += t1.x; a1[j].y += t1.y; a1[j].z += t1.z; a1[j].w += t1.w;
                }
            }
            #pragma unroll
            for (int j = 0; j < 2; j++) {
                int rr = wid + 8 * (g * 2 + j);
                out4[(size_t)(base + rr) * 64 + lane] =
                    make_float4(a0[j].x * 0.1f, a0[j].y * 0.1f, a0[j].z * 0.1f, a0[j].w * 0.1f);
                out4[(size_t)(base + rr) * 64 + lane + 32] =
                    make_float4(a1[j].x * 0.1f, a1[j].y * 0.1f, a1[j].z * 0.1f, a1[j].w * 0.1f);
            }
        }
    }
}

// ---------------- bf16x3-split tensor-core GEMM (layers 0/1) ----------------
// BM=128, BN=256, 512 threads. out = (relu?)( A_self @ W0 + mean @ W1 + bias )
// pass0: A = src[sidx[r]]  (sidx = gids[i] if RESOLVE else i),  KP columns
// pass1: A = meanbuf[i]    (sequential, pre-scaled)
template<int KP, bool RESOLVE, bool RELU>
__global__ void __launch_bounds__(512, 1)
mma_gemm(const float* __restrict__ src,
         const int*   __restrict__ gids,
         const float* __restrict__ meanbuf,
         const float* __restrict__ W0,
         const float* __restrict__ W1,
         const float* __restrict__ bias,
         float*       __restrict__ out)
{
    constexpr int LDA_U = KP / 2 + 4;
    constexpr int A_U   = 128 * LDA_U;
    constexpr int LDB_U = 264;
    constexpr int B_U   = 16 * LDB_U;

    extern __shared__ uint32_t smem[];
    uint32_t* Ahi = smem;
    uint32_t* Alo = Ahi + A_U;
    uint32_t* Bhi = Alo + A_U;
    uint32_t* Blo = Bhi + B_U;
    float*    bsm = (float*)(Blo + B_U);
    int*      sidx = (int*)(bsm + 256);

    const int tid  = threadIdx.x;
    const int lane = tid & 31;
    const int wid  = tid >> 5;
    const int wr   = wid >> 2;      // warp row 0..3
    const int wc   = wid & 3;       // warp col 0..3
    const float4* src4 = (const float4*)src;

    if (tid < 256) bsm[tid] = bias[tid];
    if (tid < 128) {
        int i = blockIdx.x * 128 + tid;
        sidx[tid] = RESOLVE ? __ldg(&gids[i]) : i;
    }
    __syncthreads();

    float acc[2][8][4];
    #pragma unroll
    for (int mt = 0; mt < 2; mt++)
        #pragma unroll
        for (int nt = 0; nt < 8; nt++)
            #pragma unroll
            for (int q = 0; q < 4; q++) acc[mt][nt][q] = 0.f;

    #pragma unroll 1
    for (int pass = 0; pass < 2; pass++) {
        const float* W = (pass == 0) ? W0 : W1;

        // ---------- stage A tile ----------
        if (pass == 0) {
            #pragma unroll
            for (int j = 0; j < 8; j++) {
                int r = wid + 16 * j;
                int g = sidx[r];
                if (KP == 128) {
                    float4 v = __ldg(&src4[(size_t)g * 32 + lane]);
                    store_split4(Ahi, Alo, r * LDA_U + 2 * lane, v);
                } else {
                    #pragma unroll
                    for (int h = 0; h < 2; h++) {
                        float4 v = __ldg(&src4[(size_t)g * 64 + lane + 32 * h]);
                        store_split4(Ahi, Alo, r * LDA_U + 2 * (lane + 32 * h), v);
                    }
                }
            }
        } else {
            const float4* m4 = (const float4*)meanbuf + (size_t)blockIdx.x * 128 * (KP / 4);
            #pragma unroll
            for (int j = 0; j < 8; j++) {
                int r = wid + 16 * j;
                if (KP == 128) {
                    float4 v = __ldg(&m4[(size_t)r * 32 + lane]);
                    store_split4(Ahi, Alo, r * LDA_U + 2 * lane, v);
                } else {
                    #pragma unroll
                    for (int h = 0; h < 2; h++) {
                        float4 v = __ldg(&m4[(size_t)r * 64 + lane + 32 * h]);
                        store_split4(Ahi, Alo, r * LDA_U + 2 * (lane + 32 * h), v);
                    }
                }
            }
        }

        // ---------- K chunks of 32: stage B (split), then MMA ----------
        #pragma unroll 1
        for (int c = 0; c < KP / 32; c++) {
            for (int e = tid; e < 16 * 256; e += 512) {
                int kp  = e >> 8;
                int col = e & 255;
                int krow = c * 32 + 2 * kp;
                float w0 = __ldg(&W[(size_t)krow * 256 + col]);
                float w1 = __ldg(&W[(size_t)(krow + 1) * 256 + col]);
                uint32_t h, l;
                split_pack(w0, w1, h, l);
                Bhi[kp * LDB_U + col] = h;
                Blo[kp * LDB_U + col] = l;
            }
            __syncthreads();

            #pragma unroll
            for (int ks = 0; ks < 2; ks++) {
                const int kpo = c * 16 + ks * 8;
                uint32_t ah[2][4], al[2][4];
                const int abase = (wr * 32 + (lane >> 2)) * LDA_U + (lane & 3) + kpo;
                #pragma unroll
                for (int mt = 0; mt < 2; mt++) {
                    int a0i = abase + mt * 16 * LDA_U;
                    ah[mt][0] = Ahi[a0i];
                    ah[mt][1] = Ahi[a0i + 8 * LDA_U];
                    ah[mt][2] = Ahi[a0i + 4];
                    ah[mt][3] = Ahi[a0i + 8 * LDA_U + 4];
                    al[mt][0] = Alo[a0i];
                    al[mt][1] = Alo[a0i + 8 * LDA_U];
                    al[mt][2] = Alo[a0i + 4];
                    al[mt][3] = Alo[a0i + 8 * LDA_U + 4];
                }
                const int bbase = (ks * 8 + (lane & 3)) * LDB_U + wc * 64 + (lane >> 2);
                #pragma unroll
                for (int nt = 0; nt < 8; nt++) {
                    int bi = bbase + nt * 8;
                    uint32_t bh0 = Bhi[bi], bh1 = Bhi[bi + 4 * LDB_U];
                    uint32_t bl0 = Blo[bi], bl1 = Blo[bi + 4 * LDB_U];
                    #pragma unroll
                    for (int mt = 0; mt < 2; mt++) {
                        MMA_BF16(acc[mt][nt], ah[mt], bh0, bh1);
                        MMA_BF16(acc[mt][nt], ah[mt], bl0, bl1);
                        MMA_BF16(acc[mt][nt], al[mt], bh0, bh1);
                    }
                }
            }
            __syncthreads();
        }
    }

    // ---------- epilogue ----------
    const int row0 = blockIdx.x * 128 + wr * 32 + (lane >> 2);
    #pragma unroll
    for (int mt = 0; mt < 2; mt++) {
        #pragma unroll
        for (int nt = 0; nt < 8; nt++) {
            int col = wc * 64 + nt * 8 + 2 * (lane & 3);
            float b0 = bsm[col], b1 = bsm[col + 1];
            float v0 = acc[mt][nt][0] + b0;
            float v1 = acc[mt][nt][1] + b1;
            float v2 = acc[mt][nt][2] + b0;
            float v3 = acc[mt][nt][3] + b1;
            if (RELU) {
                v0 = fmaxf(v0, 0.f); v1 = fmaxf(v1, 0.f);
                v2 = fmaxf(v2, 0.f); v3 = fmaxf(v3, 0.f);
            }
            int r = row0 + mt * 16;
            *(float2*)&out[(size_t)r * HIDC + col]       = make_float2(v0, v1);
            *(float2*)&out[(size_t)(r + 8) * HIDC + col] = make_float2(v2, v3);
        }
    }
}

// ---------------- fused MLP1 + MLP2 + score ----------------
__global__ void __launch_bounds__(256, 2)
mlp_fused(const float* __restrict__ h2,
          const float* __restrict__ Wp1, const float* __restrict__ bp1,
          const float* __restrict__ Wp2, const float* __restrict__ bp2,
          const float* __restrict__ Wp3, const float* __restrict__ bp3,
          float* __restrict__ out)
{
    constexpr int LDA_U = 132;
    constexpr int A_U   = 64 * LDA_U;
    constexpr int LDB_U = 264;
    constexpr int B_U   = 16 * LDB_U;

    extern __shared__ uint32_t smem[];
    uint32_t* Ahi = smem;
    uint32_t* Alo = Ahi + A_U;
    uint32_t* Bhi = Alo + A_U;
    uint32_t* Blo = Bhi + B_U;
    float* bsm1 = (float*)(Blo + B_U);
    float* bsm2 = bsm1 + 256;
    float* w3   = bsm2 + 256;
    float* sred = w3 + 256;

    const int tid  = threadIdx.x;
    const int lane = tid & 31;
    const int wid  = tid >> 5;
    const int wr   = wid >> 2;
    const int wc   = wid & 3;
    const float4* src4 = (const float4*)h2;

    bsm1[tid] = bp1[tid];
    bsm2[tid] = bp2[tid];
    w3[tid]   = Wp3[tid];
    if (tid < 64) sred[tid] = bp3[0];

    for (int r = wid; r < 64; r += 8) {
        int i = blockIdx.x * 64 + r;
        const float4* pa = src4 + (size_t)(i & (NBAT - 1)) * 64;
        const float4* pb = src4 + (size_t)(NBAT + i) * 64;
        #pragma unroll
        for (int h = 0; h < 2; h++) {
            float4 x = __ldg(pa + lane + 32 * h);
            float4 y = __ldg(pb + lane + 32 * h);
            store_split4(Ahi, Alo, r * LDA_U + 2 * (lane + 32 * h),
                         make_float4(x.x * y.x, x.y * y.y, x.z * y.z, x.w * y.w));
        }
    }

    float acc[2][8][4];

    #pragma unroll 1
    for (int layer = 0; layer < 2; layer++) {
        const float* W = (layer == 0) ? Wp1 : Wp2;

        #pragma unroll
        for (int mt = 0; mt < 2; mt++)
            #pragma unroll
            for (int nt = 0; nt < 8; nt++)
                #pragma unroll
                for (int q = 0; q < 4; q++) acc[mt][nt][q] = 0.f;

        #pragma unroll 1
        for (int c = 0; c < 8; c++) {
            for (int e = tid; e < 16 * 256; e += 256) {
                int kp  = e >> 8;
                int col = e & 255;
                int krow = c * 32 + 2 * kp;
                float w0 = __ldg(&W[(size_t)krow * 256 + col]);
                float w1 = __ldg(&W[(size_t)(krow + 1) * 256 + col]);
                uint32_t h, l;
                split_pack(w0, w1, h, l);
                Bhi[kp * LDB_U + col] = h;
                Blo[kp * LDB_U + col] = l;
            }
            __syncthreads();

            #pragma unroll
            for (int ks = 0; ks < 2; ks++) {
                const int kpo = c * 16 + ks * 8;
                uint32_t ah[2][4], al[2][4];
                const int abase = (wr * 32 + (lane >> 2)) * LDA_U + (lane & 3) + kpo;
                #pragma unroll
                for (int mt = 0; mt < 2; mt++) {
                    int a0i = abase + mt * 16 * LDA_U;
                    ah[mt][0] = Ahi[a0i];
                    ah[mt][1] = Ahi[a0i + 8 * LDA_U];
                    ah[mt][2] = Ahi[a0i + 4];
                    ah[mt][3] = Ahi[a0i + 8 * LDA_U + 4];
                    al[mt][0] = Alo[a0i];
                    al[mt][1] = Alo[a0i + 8 * LDA_U];
                    al[mt][2] = Alo[a0i + 4];
                    al[mt][3] = Alo[a0i + 8 * LDA_U + 4];
                }
                const int bbase = (ks * 8 + (lane & 3)) * LDB_U + wc * 64 + (lane >> 2);
                #pragma unroll
                for (int nt = 0; nt < 8; nt++) {
                    int bi = bbase + nt * 8;
                    uint32_t bh0 = Bhi[bi], bh1 = Bhi[bi + 4 * LDB_U];
                    uint32_t bl0 = Blo[bi], bl1 = Blo[bi + 4 * LDB_U];
                    #pragma unroll
                    for (int mt = 0; mt < 2; mt++) {
                        MMA_BF16(acc[mt][nt], ah[mt], bh0, bh1);
                        MMA_BF16(acc[mt][nt], ah[mt], bl0, bl1);
                        MMA_BF16(acc[mt][nt], al[mt], bh0, bh1);
                    }
                }
            }
            __syncthreads();
        }

        if (layer == 0) {
            #pragma unroll
            for (int mt = 0; mt < 2; mt++) {
                int r = wr * 32 + (lane >> 2) + mt * 16;
                #pragma unroll
                for (int nt = 0; nt < 8; nt++) {
                    int col = wc * 64 + nt * 8 + 2 * (lane & 3);
                    float b0 = bsm1[col], b1 = bsm1[col + 1];
                    float v0 = fmaxf(acc[mt][nt][0] + b0, 0.f);
                    float v1 = fmaxf(acc[mt][nt][1] + b1, 0.f);
                    float v2 = fmaxf(acc[mt][nt][2] + b0, 0.f);
                    float v3 = fmaxf(acc[mt][nt][3] + b1, 0.f);
                    uint32_t h, l;
                    split_pack(v0, v1, h, l);
                    Ahi[r * LDA_U + (col >> 1)] = h;
                    Alo[r * LDA_U + (col >> 1)] = l;
                    split_pack(v2, v3, h, l);
                    Ahi[(r + 8) * LDA_U + (col >> 1)] = h;
                    Alo[(r + 8) * LDA_U + (col >> 1)] = l;
                }
            }
            __syncthreads();
        }
    }

    #pragma unroll
    for (int mt = 0; mt < 2; mt++) {
        float sA = 0.f, sB = 0.f;
        #pragma unroll
        for (int nt = 0; nt < 8; nt++) {
            int col = wc * 64 + nt * 8 + 2 * (lane & 3);
            float b0 = bsm2[col], b1 = bsm2[col + 1];
            float w0 = w3[col],  w1 = w3[col + 1];
            sA += fmaxf(acc[mt][nt][0] + b0, 0.f) * w0 + fmaxf(acc[mt][nt][1] + b1, 0.f) * w1;
            sB += fmaxf(acc[mt][nt][2] + b0, 0.f) * w0 + fmaxf(acc[mt][nt][3] + b1, 0.f) * w1;
        }
        sA += __shfl_xor_sync(0xffffffffu, sA, 1);
        sA += __shfl_xor_sync(0xffffffffu, sA, 2);
        sB += __shfl_xor_sync(0xffffffffu, sB, 1);
        sB += __shfl_xor_sync(0xffffffffu, sB, 2);
        if ((lane & 3) == 0) {
            int r = wr * 32 + (lane >> 2) + mt * 16;
            atomicAdd(&sred[r], sA);
            atomicAdd(&sred[r + 8], sB);
        }
    }
    __syncthreads();
    if (tid < 64) out[blockIdx.x * 64 + tid] = sred[tid];
}

// ---------------- launch ----------------
extern "C" void kernel_launch(void* const* d_in, const int* in_sizes, int n_in,
                              void* d_out, int out_size) {
    const float* node_feat = (const float*)d_in[0];
    const int*   gids0     = (const int*)d_in[1];
    const int*   neigh0    = (const int*)d_in[2];
    const int*   neigh1    = (const int*)d_in[3];
    const float* Ws0       = (const float*)d_in[4];
    const float* Wn0       = (const float*)d_in[5];
    const float* b0        = (const float*)d_in[6];
    const float* Ws1       = (const float*)d_in[7];
    const float* Wn1       = (const float*)d_in[8];
    const float* b1        = (const float*)d_in[9];
    const float* Wp1       = (const float*)d_in[10];
    const float* bp1       = (const float*)d_in[11];
    const float* Wp2       = (const float*)d_in[12];
    const float* bp2       = (const float*)d_in[13];
    const float* Wp3       = (const float*)d_in[14];
    const float* bp3       = (const float*)d_in[15];
    float* out = (float*)d_out;

    float *h0, *h2, *mean0, *mean1;
    cudaGetSymbolAddress((void**)&h0, g_h0);
    cudaGetSymbolAddress((void**)&h2, g_h2);
    cudaGetSymbolAddress((void**)&mean0, g_mean0);
    cudaGetSymbolAddress((void**)&mean1, g_mean1);

    // smem bytes: 2*A + 2*B + bias + sidx
    const int SM128 = (2 * 128 * (128 / 2 + 4) + 2 * 16 * 264 + 256 + 128) * 4;  // 104,960
    const int SM256 = (2 * 128 * (256 / 2 + 4) + 2 * 16 * 264 + 256 + 128) * 4;  // 170,496
    const int SMMLP = (2 * 64 * 132 + 2 * 16 * 264 + 3 * 256 + 64) * 4;           // 104,704

    cudaFuncSetAttribute(mma_gemm<128, true,  true >, cudaFuncAttributeMaxDynamicSharedMemorySize, SM128);
    cudaFuncSetAttribute(mma_gemm<256, false, false>, cudaFuncAttributeMaxDynamicSharedMemorySize, SM256);
    cudaFuncSetAttribute(mlp_fused, cudaFuncAttributeMaxDynamicSharedMemorySize, SMMLP);

    // gather 0: mean0[i] = 0.1 * sum_f node_feat[gids0[neigh0[i][f]]]
    gather_mean<1, true ><<<N1C / 64, 256>>>(node_feat, gids0, neigh0, mean0);
    // layer 0: h0 = relu(node_feat[gids0[i]]@Ws0 + mean0[i]@Wn0 + b0)
    mma_gemm<128, true,  true ><<<N1C / 128, 512, SM128>>>(node_feat, gids0, mean0, Ws0, Wn0, b0, h0);
    // gather 1: mean1[i] = 0.1 * sum_f h0[neigh1[i][f]]
    gather_mean<2, false><<<N2C / 64, 256>>>(h0, nullptr, neigh1, mean1);
    // layer 1: h2 = h0[i]@Ws1 + mean1[i]@Wn1 + b1
    mma_gemm<256, false, false><<<N2C / 128, 512, SM256>>>(h0, nullptr, mean1, Ws1, Wn1, b1, h2);
    // fused MLP1+MLP2+score
    mlp_fused<<<(2 * NBAT) / 64, 256, SMMLP>>>(h2, Wp1, bp1, Wp2, bp2, Wp3, bp3, out);
}